// round 1
// baseline (speedup 1.0000x reference)
#include <cuda_runtime.h>
#include <cuda_bf16.h>

// Problem constants
#define B  2
#define C  256
#define H  200
#define W  336
#define R  1000
#define OH 14
#define OW 14
#define HW (H * W)           // 67200
#define SCALE 0.25f

// Static scratch for NHWC-transposed features: 2*200*336*256 floats = 137.6 MB
__device__ static float g_feat_nhwc[(size_t)B * HW * C];

// ---------------------------------------------------------------------------
// Kernel 1: NCHW -> NHWC transpose, per batch: (C, HW) -> (HW, C)
// ---------------------------------------------------------------------------
#define TILE 32
__global__ void nchw_to_nhwc_kernel(const float* __restrict__ src) {
    __shared__ float tile[TILE][TILE + 1];
    const int batch = blockIdx.z;
    const float* s = src + (size_t)batch * C * HW;
    float* d = g_feat_nhwc + (size_t)batch * HW * C;

    const int p0 = blockIdx.x * TILE;   // position tile (HW = 67200 = 32*2100)
    const int c0 = blockIdx.y * TILE;   // channel tile  (C  = 256  = 32*8)
    const int tx = threadIdx.x;
    const int ty = threadIdx.y;

    #pragma unroll
    for (int i = ty; i < TILE; i += 8)
        tile[i][tx] = s[(size_t)(c0 + i) * HW + p0 + tx];
    __syncthreads();
    #pragma unroll
    for (int i = ty; i < TILE; i += 8)
        d[(size_t)(p0 + i) * C + c0 + tx] = tile[tx][i];
}

// ---------------------------------------------------------------------------
// Kernel 2: ROI-align gather on NHWC features.
// Grid: R*OH blocks; 256 threads (thread = channel).
// ---------------------------------------------------------------------------
__global__ __launch_bounds__(256) void roi_align_kernel(
    const float* __restrict__ rois, float* __restrict__ out)
{
    const int blk = blockIdx.x;
    const int r  = blk / OH;
    const int oh = blk % OH;
    const int c  = threadIdx.x;

    // ROI parameters (all threads redundantly compute; cheap)
    const float bf = rois[r * 5 + 0];
    const float x1 = rois[r * 5 + 1];
    const float y1 = rois[r * 5 + 2];
    const float x2 = rois[r * 5 + 3];
    const float y2 = rois[r * 5 + 4];
    const int  b  = (int)bf;

    const float gy = ((float)oh + 0.5f) / (float)OH;
    const float fy = (y1 + gy * (y2 - y1)) * SCALE - 0.5f;
    const float y0f = floorf(fy);
    const float ly  = fy - y0f;
    const int   y0  = (int)y0f;
    const int   y1i = y0 + 1;
    const bool  vy0 = (y0  >= 0) && (y0  < H);
    const bool  vy1 = (y1i >= 0) && (y1i < H);

    const float* fbase = g_feat_nhwc + (size_t)b * HW * C + c;

    __shared__ float sout[C * OW];   // 14336 B

    #pragma unroll
    for (int ow = 0; ow < OW; ow++) {
        const float gx = ((float)ow + 0.5f) / (float)OW;
        const float fx = (x1 + gx * (x2 - x1)) * SCALE - 0.5f;
        const float x0f = floorf(fx);
        const float lx  = fx - x0f;
        const int   x0  = (int)x0f;
        const int   x1i = x0 + 1;
        const bool  vx0 = (x0  >= 0) && (x0  < W);
        const bool  vx1 = (x1i >= 0) && (x1i < W);

        float v00 = 0.f, v01 = 0.f, v10 = 0.f, v11 = 0.f;
        if (vy0 && vx0) v00 = __ldg(fbase + (size_t)(y0  * W + x0 ) * C);
        if (vy0 && vx1) v01 = __ldg(fbase + (size_t)(y0  * W + x1i) * C);
        if (vy1 && vx0) v10 = __ldg(fbase + (size_t)(y1i * W + x0 ) * C);
        if (vy1 && vx1) v11 = __ldg(fbase + (size_t)(y1i * W + x1i) * C);

        const float top = (1.0f - lx) * v00 + lx * v01;
        const float bot = (1.0f - lx) * v10 + lx * v11;
        sout[c * OW + ow] = (1.0f - ly) * top + ly * bot;
    }
    __syncthreads();

    // Coalesced-ish write: out[r][cc][oh][ow] = r*C*196 + cc*196 + oh*14 + ow
    float* obase = out + (size_t)r * C * (OH * OW) + oh * OW;
    #pragma unroll 4
    for (int i = c; i < C * OW; i += 256) {
        const int cc = i / OW;
        const int ww = i - cc * OW;
        obase[(size_t)cc * (OH * OW) + ww] = sout[i];
    }
}

// ---------------------------------------------------------------------------
extern "C" void kernel_launch(void* const* d_in, const int* in_sizes, int n_in,
                              void* d_out, int out_size) {
    // metadata order: features (34,406,400), rois (5000). Be defensive.
    const float* features = (const float*)d_in[0];
    const float* rois     = (const float*)d_in[1];
    if (n_in >= 2 && in_sizes[0] == R * 5) {
        features = (const float*)d_in[1];
        rois     = (const float*)d_in[0];
    }
    float* out = (float*)d_out;

    // 1) NCHW -> NHWC transpose
    dim3 tgrid(HW / TILE, C / TILE, B);   // (2100, 8, 2)
    dim3 tblk(TILE, 8, 1);
    nchw_to_nhwc_kernel<<<tgrid, tblk>>>(features);

    // 2) ROI-align gather
    roi_align_kernel<<<R * OH, 256>>>(rois, out);
}

// round 2
// speedup vs baseline: 1.5721x; 1.5721x over previous
#include <cuda_runtime.h>
#include <cuda_fp16.h>

// Problem constants
#define B  2
#define C  256
#define H  200
#define W  336
#define R  1000
#define OH 14
#define OW 14
#define HW (H * W)           // 67200
#define SCALE 0.25f

// Static scratch: NHWC features in fp16: 2*67200*256*2B = 68.8 MB (L2-resident)
__device__ static __half g_feat[(size_t)B * HW * C];

// ---------------------------------------------------------------------------
// Kernel 1: NCHW fp32 -> NHWC fp16 transpose.
// Tile: 64 channels x 128 positions. Read float4-coalesced, write uint2
// (4 halves) coalesced (128B per position row).
// ---------------------------------------------------------------------------
#define TC 64
#define TP 128
__global__ __launch_bounds__(256) void transpose_kernel(const float* __restrict__ src) {
    __shared__ float tile[TC][TP + 1];   // 64*129*4 = 33 KB

    const int batch = blockIdx.z;
    const int p0 = blockIdx.x * TP;      // position tile (HW/TP = 525)
    const int c0 = blockIdx.y * TC;      // channel tile  (C/TC = 4)
    const float* s = src + (size_t)batch * C * HW;
    __half*      d = g_feat + (size_t)batch * HW * C;

    const int tx = threadIdx.x;          // 0..31
    const int ty = threadIdx.y;          // 0..7

    // Read: each thread loads 8 rows (channels), float4 in position dim.
    #pragma unroll
    for (int k = 0; k < 8; k++) {
        const int c = ty + k * 8;
        const float4 v = *(const float4*)&s[(size_t)(c0 + c) * HW + p0 + tx * 4];
        float* tr = &tile[c][tx * 4];
        tr[0] = v.x; tr[1] = v.y; tr[2] = v.z; tr[3] = v.w;
    }
    __syncthreads();

    // Write: per position, 64 halves = 128B. Each thread emits one uint2
    // (4 halves); 16 c4-lanes x 16 positions per pass, 8 passes.
    const int tid = ty * 32 + tx;
    const int c4 = tid & 15;
    const int pbase = tid >> 4;
    #pragma unroll
    for (int k = 0; k < 8; k++) {
        const int p = pbase + k * 16;
        const __half2 h0 = __floats2half2_rn(tile[c4 * 4 + 0][p], tile[c4 * 4 + 1][p]);
        const __half2 h1 = __floats2half2_rn(tile[c4 * 4 + 2][p], tile[c4 * 4 + 3][p]);
        uint2 u;
        u.x = *reinterpret_cast<const unsigned int*>(&h0);
        u.y = *reinterpret_cast<const unsigned int*>(&h1);
        *reinterpret_cast<uint2*>(d + (size_t)(p0 + p) * C + c0 + c4 * 4) = u;
    }
}

// ---------------------------------------------------------------------------
// Kernel 2: ROI-align gather on fp16 NHWC features.
// Block = (roi, oh); 256 threads = 64 channel-groups (4ch each) x 4 ow-lanes.
// ---------------------------------------------------------------------------
#define SOUT_STRIDE 260   // C + 4 pad (keeps float4 alignment, breaks bank conflicts)

__global__ __launch_bounds__(256) void roi_gather_kernel(
    const float* __restrict__ rois, float* __restrict__ out)
{
    const int blk = blockIdx.x;
    const int r  = blk / OH;
    const int oh = blk % OH;
    const int t  = threadIdx.x;
    const int cg  = t & 63;    // channel group: channels 4cg..4cg+3
    const int owl = t >> 6;    // 0..3

    const float bf = rois[r * 5 + 0];
    const float x1 = rois[r * 5 + 1];
    const float y1 = rois[r * 5 + 2];
    const float x2 = rois[r * 5 + 3];
    const float y2 = rois[r * 5 + 4];
    const int  b  = (int)bf;

    const float gy  = ((float)oh + 0.5f) / (float)OH;
    const float fy  = (y1 + gy * (y2 - y1)) * SCALE - 0.5f;
    const float y0f = floorf(fy);
    const float ly  = fy - y0f;
    const int   y0  = (int)y0f;
    const int   y1i = y0 + 1;
    const bool  vy0 = (y0  >= 0) && (y0  < H);
    const bool  vy1 = (y1i >= 0) && (y1i < H);

    // uint2 = 4 halves; per batch HW*C/4 = HW*64 uint2 elements.
    const uint2* f2 = reinterpret_cast<const uint2*>(g_feat) + (size_t)b * HW * 64;

    __shared__ float sout[OW * SOUT_STRIDE];   // ~14.6 KB

    for (int ow = owl; ow < OW; ow += 4) {
        const float gx  = ((float)ow + 0.5f) / (float)OW;
        const float fx  = (x1 + gx * (x2 - x1)) * SCALE - 0.5f;
        const float x0f = floorf(fx);
        const float lx  = fx - x0f;
        const int   x0  = (int)x0f;
        const int   x1i = x0 + 1;
        const bool  vx0 = (x0  >= 0) && (x0  < W);
        const bool  vx1 = (x1i >= 0) && (x1i < W);

        float o0 = 0.f, o1 = 0.f, o2 = 0.f, o3 = 0.f;

        #define ACCUM(Y, X, WGT, VALID)                                        \
            if (VALID) {                                                       \
                const uint2 u = __ldg(&f2[(size_t)((Y) * W + (X)) * 64 + cg]); \
                const __half2 ha = *reinterpret_cast<const __half2*>(&u.x);    \
                const __half2 hb = *reinterpret_cast<const __half2*>(&u.y);    \
                const float2 fa = __half22float2(ha);                          \
                const float2 fb = __half22float2(hb);                          \
                const float w = (WGT);                                         \
                o0 = fmaf(w, fa.x, o0); o1 = fmaf(w, fa.y, o1);                \
                o2 = fmaf(w, fb.x, o2); o3 = fmaf(w, fb.y, o3);                \
            }

        ACCUM(y0,  x0,  (1.f - ly) * (1.f - lx), vy0 && vx0);
        ACCUM(y0,  x1i, (1.f - ly) * lx,         vy0 && vx1);
        ACCUM(y1i, x0,  ly * (1.f - lx),         vy1 && vx0);
        ACCUM(y1i, x1i, ly * lx,                 vy1 && vx1);
        #undef ACCUM

        *reinterpret_cast<float4*>(&sout[ow * SOUT_STRIDE + cg * 4]) =
            make_float4(o0, o1, o2, o3);
    }
    __syncthreads();

    // Write-out: out[r][cc][oh][ww]; consecutive i -> near-contiguous gmem.
    float* obase = out + (size_t)r * C * (OH * OW) + oh * OW;
    #pragma unroll 4
    for (int i = t; i < C * OW; i += 256) {
        const int cc = i / OW;
        const int ww = i - cc * OW;
        obase[(size_t)cc * (OH * OW) + ww] = sout[ww * SOUT_STRIDE + cc];
    }
}

// ---------------------------------------------------------------------------
extern "C" void kernel_launch(void* const* d_in, const int* in_sizes, int n_in,
                              void* d_out, int out_size) {
    const float* features = (const float*)d_in[0];
    const float* rois     = (const float*)d_in[1];
    if (n_in >= 2 && in_sizes[0] == R * 5) {
        features = (const float*)d_in[1];
        rois     = (const float*)d_in[0];
    }
    float* out = (float*)d_out;

    dim3 tgrid(HW / TP, C / TC, B);   // (525, 4, 2)
    dim3 tblk(32, 8, 1);
    transpose_kernel<<<tgrid, tblk>>>(features);

    roi_gather_kernel<<<R * OH, 256>>>(rois, out);
}

// round 3
// speedup vs baseline: 1.5844x; 1.0078x over previous
#include <cuda_runtime.h>
#include <cuda_fp16.h>

// Problem constants
#define B  2
#define C  256
#define H  200
#define W  336
#define R  1000
#define OH 14
#define OW 14
#define HW (H * W)           // 67200
#define SCALE 0.25f

// NHWC features in fp16: 2*67200*256*2B = 68.8 MB (mostly L2-resident)
__device__ static __half g_feat[(size_t)B * HW * C];

// ---------------------------------------------------------------------------
// Kernel 1: NCHW fp32 -> NHWC fp16 transpose, fully vectorized.
// Tile 64ch x 64pos, 256 threads. 4x4 register micro-transpose, XOR-swizzled
// position-major smem tile (stride 68 words): STS.128 and LDS.128 both
// conflict-free.
// ---------------------------------------------------------------------------
#define TSTRIDE 68
__global__ __launch_bounds__(256) void transpose_kernel(const float* __restrict__ src) {
    __shared__ float tileT[64 * TSTRIDE];   // 17.4 KB, position-major

    const int batch = blockIdx.z;
    const int p0 = blockIdx.x * 64;      // HW/64 = 1050
    const int c0 = blockIdx.y * 64;      // C/64 = 4
    const float* s = src + (size_t)batch * C * HW;
    __half*      d = g_feat + (size_t)batch * HW * C;

    // Read phase: tx = position-quad (fast, coalesced), ty = channel-quad.
    {
        const int tx = threadIdx.x & 15;
        const int ty = threadIdx.x >> 4;
        const float* rb = s + (size_t)(c0 + ty * 4) * HW + p0 + tx * 4;
        const float4 v0 = *(const float4*)(rb);
        const float4 v1 = *(const float4*)(rb + HW);
        const float4 v2 = *(const float4*)(rb + 2 * (size_t)HW);
        const float4 v3 = *(const float4*)(rb + 3 * (size_t)HW);

        // p = 4*tx + i; swizzled column: ((ty ^ (p>>2)) & 15) * 4 = ((ty^tx)&15)*4
        float* wb = &tileT[(4 * tx) * TSTRIDE + 4 * ((ty ^ tx) & 15)];
        *(float4*)(wb + 0 * TSTRIDE) = make_float4(v0.x, v1.x, v2.x, v3.x);
        *(float4*)(wb + 1 * TSTRIDE) = make_float4(v0.y, v1.y, v2.y, v3.y);
        *(float4*)(wb + 2 * TSTRIDE) = make_float4(v0.z, v1.z, v2.z, v3.z);
        *(float4*)(wb + 3 * TSTRIDE) = make_float4(v0.w, v1.w, v2.w, v3.w);
    }
    __syncthreads();

    // Write phase: c4 = channel-quad (fast -> contiguous gmem), pr = position.
    {
        const int c4 = threadIdx.x & 15;
        const int pr = threadIdx.x >> 4;
        #pragma unroll
        for (int k = 0; k < 4; k++) {
            const int p = pr + k * 16;
            const float4 w = *(const float4*)&tileT[p * TSTRIDE + 4 * ((c4 ^ (p >> 2)) & 15)];
            const __half2 h0 = __floats2half2_rn(w.x, w.y);
            const __half2 h1 = __floats2half2_rn(w.z, w.w);
            uint2 u;
            u.x = *reinterpret_cast<const unsigned int*>(&h0);
            u.y = *reinterpret_cast<const unsigned int*>(&h1);
            *reinterpret_cast<uint2*>(d + (size_t)(p0 + p) * C + c0 + c4 * 4) = u;
        }
    }
}

// ---------------------------------------------------------------------------
// Kernel 2: ROI-align gather on fp16 NHWC features.
// Block = (roi, oh-pair): grid R*7. 256 threads = 32 channel-groups (8ch,
// uint4 loads) x 8 sample lanes over 28 samples (2 oh x 14 ow).
// ---------------------------------------------------------------------------
#define CPAD 260

__global__ __launch_bounds__(256) void roi_gather_kernel(
    const float* __restrict__ rois, float* __restrict__ out)
{
    const int blk  = blockIdx.x;
    const int r    = blk / 7;
    const int oh0  = (blk - r * 7) * 2;
    const int t    = threadIdx.x;
    const int cg   = t & 31;    // channel group: channels 8cg..8cg+7
    const int lane = t >> 5;    // 0..7

    const float bf = __ldg(&rois[r * 5 + 0]);
    const float x1 = __ldg(&rois[r * 5 + 1]);
    const float y1 = __ldg(&rois[r * 5 + 2]);
    const float x2 = __ldg(&rois[r * 5 + 3]);
    const float y2 = __ldg(&rois[r * 5 + 4]);
    const int  b   = (int)bf;

    // uint4 = 8 halves; per batch HW*32 uint4 elements.
    const uint4* f4 = reinterpret_cast<const uint4*>(g_feat) + (size_t)b * HW * 32;

    __shared__ float sout[28 * CPAD];   // 29.1 KB

    for (int s = lane; s < 28; s += 8) {
        const int oh = oh0 + (s >= 14 ? 1 : 0);
        const int ow = (s >= 14) ? s - 14 : s;

        const float gy  = ((float)oh + 0.5f) * (1.0f / OH);
        const float fy  = (y1 + gy * (y2 - y1)) * SCALE - 0.5f;
        const float y0f = floorf(fy);
        const float ly  = fy - y0f;
        const int   yi0 = (int)y0f;
        const int   yi1 = yi0 + 1;
        const bool  vy0 = (yi0 >= 0) && (yi0 < H);
        const bool  vy1 = (yi1 >= 0) && (yi1 < H);

        const float gx  = ((float)ow + 0.5f) * (1.0f / OW);
        const float fx  = (x1 + gx * (x2 - x1)) * SCALE - 0.5f;
        const float x0f = floorf(fx);
        const float lx  = fx - x0f;
        const int   xi0 = (int)x0f;
        const int   xi1 = xi0 + 1;
        const bool  vx0 = (xi0 >= 0) && (xi0 < W);
        const bool  vx1 = (xi1 >= 0) && (xi1 < W);

        float o0 = 0.f, o1 = 0.f, o2 = 0.f, o3 = 0.f;
        float o4 = 0.f, o5 = 0.f, o6 = 0.f, o7 = 0.f;

        #define ACCUM(Y, X, WGT, VALID)                                          \
            if (VALID) {                                                         \
                const uint4 u = __ldg(&f4[(size_t)((Y) * W + (X)) * 32 + cg]);   \
                const float2 fa = __half22float2(*reinterpret_cast<const __half2*>(&u.x)); \
                const float2 fb = __half22float2(*reinterpret_cast<const __half2*>(&u.y)); \
                const float2 fc = __half22float2(*reinterpret_cast<const __half2*>(&u.z)); \
                const float2 fd = __half22float2(*reinterpret_cast<const __half2*>(&u.w)); \
                const float w = (WGT);                                           \
                o0 = fmaf(w, fa.x, o0); o1 = fmaf(w, fa.y, o1);                  \
                o2 = fmaf(w, fb.x, o2); o3 = fmaf(w, fb.y, o3);                  \
                o4 = fmaf(w, fc.x, o4); o5 = fmaf(w, fc.y, o5);                  \
                o6 = fmaf(w, fd.x, o6); o7 = fmaf(w, fd.y, o7);                  \
            }

        ACCUM(yi0, xi0, (1.f - ly) * (1.f - lx), vy0 && vx0);
        ACCUM(yi0, xi1, (1.f - ly) * lx,         vy0 && vx1);
        ACCUM(yi1, xi0, ly * (1.f - lx),         vy1 && vx0);
        ACCUM(yi1, xi1, ly * lx,                 vy1 && vx1);
        #undef ACCUM

        float* sb = &sout[s * CPAD + cg * 8];
        *(float4*)(sb + 0) = make_float4(o0, o1, o2, o3);
        *(float4*)(sb + 4) = make_float4(o4, o5, o6, o7);
    }
    __syncthreads();

    // Writeback: out[r][cc][oh0*14 .. oh0*14+28) -> 112B contiguous per cc.
    // 1792 float4 groups: i4 -> (cc = i4/7, j = (i4%7)*4).
    float* obase = out + (size_t)r * C * (OH * OW) + oh0 * OW;
    #pragma unroll
    for (int k = 0; k < 7; k++) {
        const int i4 = t + k * 256;
        const int cc = i4 / 7;
        const int j  = (i4 - cc * 7) * 4;
        float4 w;
        w.x = sout[(j + 0) * CPAD + cc];
        w.y = sout[(j + 1) * CPAD + cc];
        w.z = sout[(j + 2) * CPAD + cc];
        w.w = sout[(j + 3) * CPAD + cc];
        *reinterpret_cast<float4*>(&obase[(size_t)cc * (OH * OW) + j]) = w;
    }
}

// ---------------------------------------------------------------------------
extern "C" void kernel_launch(void* const* d_in, const int* in_sizes, int n_in,
                              void* d_out, int out_size) {
    const float* features = (const float*)d_in[0];
    const float* rois     = (const float*)d_in[1];
    if (n_in >= 2 && in_sizes[0] == R * 5) {
        features = (const float*)d_in[1];
        rois     = (const float*)d_in[0];
    }
    float* out = (float*)d_out;

    dim3 tgrid(HW / 64, C / 64, B);   // (1050, 4, 2)
    transpose_kernel<<<tgrid, 256>>>(features);

    roi_gather_kernel<<<R * 7, 256>>>(rois, out);
}

// round 5
// speedup vs baseline: 1.7517x; 1.1056x over previous
#include <cuda_runtime.h>
#include <cuda_fp16.h>

// Problem constants
#define B  2
#define C  256
#define H  200
#define W  336
#define R  1000
#define OH 14
#define OW 14
#define HW (H * W)           // 67200
#define SCALE 0.25f

// NHWC features in fp16: 2*67200*256*2B = 68.8 MB (kept L2-resident)
__device__ static __half g_feat[(size_t)B * HW * C];

// ---------------------------------------------------------------------------
// Kernel 1: NCHW fp32 -> NHWC fp16 transpose (4x4 register micro-transpose,
// XOR-swizzled smem). Source reads streamed (__ldcs): single use.
// ---------------------------------------------------------------------------
#define TSTRIDE 68
__global__ __launch_bounds__(256) void transpose_kernel(const float* __restrict__ src) {
    __shared__ float tileT[64 * TSTRIDE];

    const int batch = blockIdx.z;
    const int p0 = blockIdx.x * 64;
    const int c0 = blockIdx.y * 64;
    const float* s = src + (size_t)batch * C * HW;
    __half*      d = g_feat + (size_t)batch * HW * C;

    {
        const int tx = threadIdx.x & 15;
        const int ty = threadIdx.x >> 4;
        const float* rb = s + (size_t)(c0 + ty * 4) * HW + p0 + tx * 4;
        const float4 v0 = __ldcs((const float4*)(rb));
        const float4 v1 = __ldcs((const float4*)(rb + HW));
        const float4 v2 = __ldcs((const float4*)(rb + 2 * (size_t)HW));
        const float4 v3 = __ldcs((const float4*)(rb + 3 * (size_t)HW));

        float* wb = &tileT[(4 * tx) * TSTRIDE + 4 * ((ty ^ tx) & 15)];
        *(float4*)(wb + 0 * TSTRIDE) = make_float4(v0.x, v1.x, v2.x, v3.x);
        *(float4*)(wb + 1 * TSTRIDE) = make_float4(v0.y, v1.y, v2.y, v3.y);
        *(float4*)(wb + 2 * TSTRIDE) = make_float4(v0.z, v1.z, v2.z, v3.z);
        *(float4*)(wb + 3 * TSTRIDE) = make_float4(v0.w, v1.w, v2.w, v3.w);
    }
    __syncthreads();

    {
        const int c4 = threadIdx.x & 15;
        const int pr = threadIdx.x >> 4;
        #pragma unroll
        for (int k = 0; k < 4; k++) {
            const int p = pr + k * 16;
            const float4 w = *(const float4*)&tileT[p * TSTRIDE + 4 * ((c4 ^ (p >> 2)) & 15)];
            const __half2 h0 = __floats2half2_rn(w.x, w.y);
            const __half2 h1 = __floats2half2_rn(w.z, w.w);
            uint2 u;
            u.x = *reinterpret_cast<const unsigned int*>(&h0);
            u.y = *reinterpret_cast<const unsigned int*>(&h1);
            *reinterpret_cast<uint2*>(d + (size_t)(p0 + p) * C + c0 + c4 * 4) = u;
        }
    }
}

// ---------------------------------------------------------------------------
// Kernel 2: ROI-align gather. Block = (roi, oh-pair), 448 threads =
// 32 channel-groups (8ch, uint4 loads) x 14 lanes; each lane does exactly 2
// of the 28 (oh,ow) samples.
// smem row (per sample): low quads (ch 8g..8g+3) at word 4g, high quads
// (ch 8g+4..8g+7) at word 128+4g; row stride 260 (float4-aligned).
//   - store:   STS.128 contiguous across warp  -> conflict-free
//   - writeback: one LDS.128 per thread, consecutive jj lanes -> disjoint
//     4-bank groups (260 mod 32 = 4)           -> conflict-free
// Output stores streamed (__stcs) to keep features L2-resident.
// ---------------------------------------------------------------------------
#define CPAD 260

__global__ __launch_bounds__(448) void roi_gather_kernel(
    const float* __restrict__ rois, float* __restrict__ out)
{
    const int blk  = blockIdx.x;
    const int r    = blk / 7;
    const int oh0  = (blk - r * 7) * 2;
    const int t    = threadIdx.x;
    const int cg   = t & 31;    // channel group: channels 8cg..8cg+7
    const int lane = t >> 5;    // 0..13 = ow

    const float bf = __ldg(&rois[r * 5 + 0]);
    const float x1 = __ldg(&rois[r * 5 + 1]);
    const float y1 = __ldg(&rois[r * 5 + 2]);
    const float x2 = __ldg(&rois[r * 5 + 3]);
    const float y2 = __ldg(&rois[r * 5 + 4]);
    const int  b   = (int)bf;

    const uint4* f4 = reinterpret_cast<const uint4*>(g_feat) + (size_t)b * HW * 32;

    __shared__ float sout[28 * CPAD];   // 29.1 KB

    #pragma unroll
    for (int k = 0; k < 2; k++) {
        const int s  = lane + k * 14;   // = (oh - oh0)*14 + ow
        const int oh = oh0 + k;
        const int ow = lane;

        const float gy  = ((float)oh + 0.5f) * (1.0f / OH);
        const float fy  = (y1 + gy * (y2 - y1)) * SCALE - 0.5f;
        const float y0f = floorf(fy);
        const float ly  = fy - y0f;
        const int   yi0 = (int)y0f;
        const int   yi1 = yi0 + 1;
        const bool  vy0 = (yi0 >= 0) && (yi0 < H);
        const bool  vy1 = (yi1 >= 0) && (yi1 < H);

        const float gx  = ((float)ow + 0.5f) * (1.0f / OW);
        const float fx  = (x1 + gx * (x2 - x1)) * SCALE - 0.5f;
        const float x0f = floorf(fx);
        const float lx  = fx - x0f;
        const int   xi0 = (int)x0f;
        const int   xi1 = xi0 + 1;
        const bool  vx0 = (xi0 >= 0) && (xi0 < W);
        const bool  vx1 = (xi1 >= 0) && (xi1 < W);

        float o0 = 0.f, o1 = 0.f, o2 = 0.f, o3 = 0.f;
        float o4 = 0.f, o5 = 0.f, o6 = 0.f, o7 = 0.f;

        #define ACCUM(Y, X, WGT, VALID)                                          \
            if (VALID) {                                                         \
                const uint4 u = __ldg(&f4[(size_t)((Y) * W + (X)) * 32 + cg]);   \
                const float2 fa = __half22float2(*reinterpret_cast<const __half2*>(&u.x)); \
                const float2 fb = __half22float2(*reinterpret_cast<const __half2*>(&u.y)); \
                const float2 fc = __half22float2(*reinterpret_cast<const __half2*>(&u.z)); \
                const float2 fd = __half22float2(*reinterpret_cast<const __half2*>(&u.w)); \
                const float w = (WGT);                                           \
                o0 = fmaf(w, fa.x, o0); o1 = fmaf(w, fa.y, o1);                  \
                o2 = fmaf(w, fb.x, o2); o3 = fmaf(w, fb.y, o3);                  \
                o4 = fmaf(w, fc.x, o4); o5 = fmaf(w, fc.y, o5);                  \
                o6 = fmaf(w, fd.x, o6); o7 = fmaf(w, fd.y, o7);                  \
            }

        ACCUM(yi0, xi0, (1.f - ly) * (1.f - lx), vy0 && vx0);
        ACCUM(yi0, xi1, (1.f - ly) * lx,         vy0 && vx1);
        ACCUM(yi1, xi0, ly * (1.f - lx),         vy1 && vx0);
        ACCUM(yi1, xi1, ly * lx,                 vy1 && vx1);
        #undef ACCUM

        float* sb = &sout[s * CPAD];
        *(float4*)(sb + cg * 4)       = make_float4(o0, o1, o2, o3);
        *(float4*)(sb + 128 + cg * 4) = make_float4(o4, o5, o6, o7);
    }
    __syncthreads();

    // Writeback: 1792 units = 64 channel-quads x 28 samples; 4 per thread.
    // Channel quad q: channels 4q..4q+3 live at row word off4(q).
    float* obase = out + (size_t)r * C * (OH * OW) + oh0 * OW;
    #pragma unroll
    for (int k = 0; k < 4; k++) {
        const int i4 = t + k * 448;
        const int q  = i4 / 28;          // 0..63
        const int jj = i4 - q * 28;      // 0..27
        const int off4 = ((q & 1) << 7) + ((q >> 1) << 2);
        const float4 w = *(const float4*)&sout[jj * CPAD + off4];
        float* ob = obase + (size_t)(q * 4) * (OH * OW) + jj;
        __stcs(ob,                 w.x);
        __stcs(ob +     (OH * OW), w.y);
        __stcs(ob + 2 * (OH * OW), w.z);
        __stcs(ob + 3 * (OH * OW), w.w);
    }
}

// ---------------------------------------------------------------------------
extern "C" void kernel_launch(void* const* d_in, const int* in_sizes, int n_in,
                              void* d_out, int out_size) {
    const float* features = (const float*)d_in[0];
    const float* rois     = (const float*)d_in[1];
    if (n_in >= 2 && in_sizes[0] == R * 5) {
        features = (const float*)d_in[1];
        rois     = (const float*)d_in[0];
    }
    float* out = (float*)d_out;

    dim3 tgrid(HW / 64, C / 64, B);   // (1050, 4, 2)
    transpose_kernel<<<tgrid, 256>>>(features);

    roi_gather_kernel<<<R * 7, 448>>>(rois, out);
}

// round 6
// speedup vs baseline: 1.9721x; 1.1258x over previous
#include <cuda_runtime.h>
#include <cuda_fp16.h>

// Problem constants
#define B  2
#define C  256
#define H  200
#define W  336
#define R  1000
#define OH 14
#define OW 14
#define HW (H * W)           // 67200
#define SCALE 0.25f

// NHWC features in fp16: 2*67200*256*2B = 68.8 MB (kept L2-resident)
__device__ static __half g_feat[(size_t)B * HW * C];

// ---------------------------------------------------------------------------
// Kernel 1: NCHW fp32 -> NHWC fp16 transpose (4x4 register micro-transpose,
// XOR-swizzled smem). Source reads streamed (__ldcs): single use.
// ---------------------------------------------------------------------------
#define TSTRIDE 68
__global__ __launch_bounds__(256) void transpose_kernel(const float* __restrict__ src) {
    __shared__ float tileT[64 * TSTRIDE];

    const int batch = blockIdx.z;
    const int p0 = blockIdx.x * 64;
    const int c0 = blockIdx.y * 64;
    const float* s = src + (size_t)batch * C * HW;
    __half*      d = g_feat + (size_t)batch * HW * C;

    {
        const int tx = threadIdx.x & 15;
        const int ty = threadIdx.x >> 4;
        const float* rb = s + (size_t)(c0 + ty * 4) * HW + p0 + tx * 4;
        const float4 v0 = __ldcs((const float4*)(rb));
        const float4 v1 = __ldcs((const float4*)(rb + HW));
        const float4 v2 = __ldcs((const float4*)(rb + 2 * (size_t)HW));
        const float4 v3 = __ldcs((const float4*)(rb + 3 * (size_t)HW));

        float* wb = &tileT[(4 * tx) * TSTRIDE + 4 * ((ty ^ tx) & 15)];
        *(float4*)(wb + 0 * TSTRIDE) = make_float4(v0.x, v1.x, v2.x, v3.x);
        *(float4*)(wb + 1 * TSTRIDE) = make_float4(v0.y, v1.y, v2.y, v3.y);
        *(float4*)(wb + 2 * TSTRIDE) = make_float4(v0.z, v1.z, v2.z, v3.z);
        *(float4*)(wb + 3 * TSTRIDE) = make_float4(v0.w, v1.w, v2.w, v3.w);
    }
    __syncthreads();

    {
        const int c4 = threadIdx.x & 15;
        const int pr = threadIdx.x >> 4;
        #pragma unroll
        for (int k = 0; k < 4; k++) {
            const int p = pr + k * 16;
            const float4 w = *(const float4*)&tileT[p * TSTRIDE + 4 * ((c4 ^ (p >> 2)) & 15)];
            const __half2 h0 = __floats2half2_rn(w.x, w.y);
            const __half2 h1 = __floats2half2_rn(w.z, w.w);
            uint2 u;
            u.x = *reinterpret_cast<const unsigned int*>(&h0);
            u.y = *reinterpret_cast<const unsigned int*>(&h1);
            *reinterpret_cast<uint2*>(d + (size_t)(p0 + p) * C + c0 + c4 * 4) = u;
        }
    }
}

// ---------------------------------------------------------------------------
// Kernel 2: ROI-align gather. Block = (roi, oh-pair), 448 threads =
// 32 channel-groups (8ch, uint4) x 14 lanes; each lane: exactly 2 samples.
// Branchless corner loads: indices clamped, weights zeroed when invalid ->
// 4 unconditional LDG.128 per sample, front-batched (MLP=4).
// ---------------------------------------------------------------------------
#define CPAD 260

__global__ __launch_bounds__(448, 4) void roi_gather_kernel(
    const float* __restrict__ rois, float* __restrict__ out)
{
    const int blk  = blockIdx.x;
    const int r    = blk / 7;
    const int oh0  = (blk - r * 7) * 2;
    const int t    = threadIdx.x;
    const int cg   = t & 31;    // channel group: channels 8cg..8cg+7
    const int lane = t >> 5;    // 0..13 = ow

    const float bf = __ldg(&rois[r * 5 + 0]);
    const float x1 = __ldg(&rois[r * 5 + 1]);
    const float y1 = __ldg(&rois[r * 5 + 2]);
    const float x2 = __ldg(&rois[r * 5 + 3]);
    const float y2 = __ldg(&rois[r * 5 + 4]);
    const int  b   = (int)bf;

    const uint4* f4 = reinterpret_cast<const uint4*>(g_feat) + (size_t)b * HW * 32;

    __shared__ float sout[28 * CPAD];   // 29.1 KB

    // x-geometry is the same for both samples (same ow)
    const float gx  = ((float)lane + 0.5f) * (1.0f / OW);
    const float fx  = (x1 + gx * (x2 - x1)) * SCALE - 0.5f;
    const float x0f = floorf(fx);
    const float lx  = fx - x0f;
    const int   xi0 = (int)x0f;
    const int   xi1 = xi0 + 1;
    const float vx0 = (xi0 >= 0 && xi0 < W) ? 1.0f : 0.0f;
    const float vx1 = (xi1 >= 0 && xi1 < W) ? 1.0f : 0.0f;
    const int   x0c = min(max(xi0, 0), W - 1);
    const int   x1c = min(max(xi1, 0), W - 1);
    const float wx0 = (1.0f - lx) * vx0;
    const float wx1 = lx * vx1;

    #pragma unroll
    for (int k = 0; k < 2; k++) {
        const int s  = lane + k * 14;
        const int oh = oh0 + k;

        const float gy  = ((float)oh + 0.5f) * (1.0f / OH);
        const float fy  = (y1 + gy * (y2 - y1)) * SCALE - 0.5f;
        const float y0f = floorf(fy);
        const float ly  = fy - y0f;
        const int   yi0 = (int)y0f;
        const int   yi1 = yi0 + 1;
        const float vy0 = (yi0 >= 0 && yi0 < H) ? 1.0f : 0.0f;
        const float vy1 = (yi1 >= 0 && yi1 < H) ? 1.0f : 0.0f;
        const int   y0c = min(max(yi0, 0), H - 1);
        const int   y1c = min(max(yi1, 0), H - 1);

        const float w00 = (1.0f - ly) * vy0 * wx0;
        const float w01 = (1.0f - ly) * vy0 * wx1;
        const float w10 = ly * vy1 * wx0;
        const float w11 = ly * vy1 * wx1;

        // Unconditional, front-batched corner loads (MLP=4)
        const uint4 u00 = __ldg(&f4[(size_t)(y0c * W + x0c) * 32 + cg]);
        const uint4 u01 = __ldg(&f4[(size_t)(y0c * W + x1c) * 32 + cg]);
        const uint4 u10 = __ldg(&f4[(size_t)(y1c * W + x0c) * 32 + cg]);
        const uint4 u11 = __ldg(&f4[(size_t)(y1c * W + x1c) * 32 + cg]);

        float o0, o1, o2, o3, o4, o5, o6, o7;
        #define BLEND(CMP, OA, OB)                                                        \
            {                                                                             \
                const float2 a = __half22float2(*reinterpret_cast<const __half2*>(&u00.CMP)); \
                const float2 bq = __half22float2(*reinterpret_cast<const __half2*>(&u01.CMP)); \
                const float2 c = __half22float2(*reinterpret_cast<const __half2*>(&u10.CMP)); \
                const float2 dq = __half22float2(*reinterpret_cast<const __half2*>(&u11.CMP)); \
                OA = fmaf(w00, a.x, fmaf(w01, bq.x, fmaf(w10, c.x, w11 * dq.x)));         \
                OB = fmaf(w00, a.y, fmaf(w01, bq.y, fmaf(w10, c.y, w11 * dq.y)));         \
            }
        BLEND(x, o0, o1)
        BLEND(y, o2, o3)
        BLEND(z, o4, o5)
        BLEND(w, o6, o7)
        #undef BLEND

        float* sb = &sout[s * CPAD];
        *(float4*)(sb + cg * 4)       = make_float4(o0, o1, o2, o3);
        *(float4*)(sb + 128 + cg * 4) = make_float4(o4, o5, o6, o7);
    }
    __syncthreads();

    // Writeback: 1792 units = 64 channel-quads x 28 samples; 4 per thread.
    float* obase = out + (size_t)r * C * (OH * OW) + oh0 * OW;
    #pragma unroll
    for (int k = 0; k < 4; k++) {
        const int i4 = t + k * 448;
        const int q  = i4 / 28;          // 0..63
        const int jj = i4 - q * 28;      // 0..27
        const int off4 = ((q & 1) << 7) + ((q >> 1) << 2);
        const float4 w = *(const float4*)&sout[jj * CPAD + off4];
        float* ob = obase + (size_t)(q * 4) * (OH * OW) + jj;
        __stcs(ob,                 w.x);
        __stcs(ob +     (OH * OW), w.y);
        __stcs(ob + 2 * (OH * OW), w.z);
        __stcs(ob + 3 * (OH * OW), w.w);
    }
}

// ---------------------------------------------------------------------------
extern "C" void kernel_launch(void* const* d_in, const int* in_sizes, int n_in,
                              void* d_out, int out_size) {
    const float* features = (const float*)d_in[0];
    const float* rois     = (const float*)d_in[1];
    if (n_in >= 2 && in_sizes[0] == R * 5) {
        features = (const float*)d_in[1];
        rois     = (const float*)d_in[0];
    }
    float* out = (float*)d_out;

    dim3 tgrid(HW / 64, C / 64, B);   // (1050, 4, 2)
    transpose_kernel<<<tgrid, 256>>>(features);

    roi_gather_kernel<<<R * 7, 448>>>(rois, out);
}